// round 10
// baseline (speedup 1.0000x reference)
#include <cuda_runtime.h>
#include <cstdint>

#define N_NODES 100000
#define IN_CH 128
#define HID 32
#define MAX_E 3400000
#define SCAN_B 1024
#define MAX_PART 128

// ---- scratch: device globals. Referenced ONLY from device code. ----
__device__ __align__(16) float g_h[N_NODES * HID];    // hs = (x@W)*dinv per layer
__device__ __align__(16) float g_acc[N_NODES * HID];  // layer-1 aggregated output
__device__ int   g_deg[N_NODES];
__device__ float g_dinv[N_NODES];
__device__ int   g_off[N_NODES + 1];
__device__ int   g_csr_src[MAX_E];
__device__ int   g_pos[MAX_E];        // edge rank within its dst bucket
__device__ int   g_part[MAX_PART];
__device__ int   g_partoff[MAX_PART];
__device__ int   g_is64;

// ---- packed f32x2 helpers (Blackwell FFMA2) ----
__device__ __forceinline__ unsigned long long pack2(float a, float b) {
    unsigned long long r;
    asm("mov.b64 %0, {%1, %2};" : "=l"(r) : "f"(a), "f"(b));
    return r;
}
__device__ __forceinline__ unsigned long long fma2(unsigned long long a,
                                                   unsigned long long b,
                                                   unsigned long long c) {
    unsigned long long d;
    asm("fma.rn.f32x2 %0, %1, %2, %3;" : "=l"(d) : "l"(a), "l"(b), "l"(c));
    return d;
}
__device__ __forceinline__ float2 unpack2(unsigned long long v) {
    float2 f;
    asm("mov.b64 {%0, %1}, %2;" : "=f"(f.x), "=f"(f.y) : "l"(v));
    return f;
}

// ---------------- dtype probe + zero deg (fused) ----------------
__global__ void k_detect_zero(const int* __restrict__ ei32, int E, int n) {
    int i = blockIdx.x * blockDim.x + threadIdx.x;
    if (i < n) g_deg[i] = 0;
    if (blockIdx.x == 0) {
        __shared__ int nz;
        if (threadIdx.x == 0) nz = 0;
        __syncthreads();
        int m = (E > 256) ? 256 : E;
        if (threadIdx.x < m) {
            if (ei32[2 * threadIdx.x + 1] != 0) nz = 1;  // benign race
        }
        __syncthreads();
        if (threadIdx.x == 0) g_is64 = (nz == 0);
    }
}

// ---------------- degree + per-edge bucket rank ----------------
__global__ void k_deg(const int* __restrict__ ei32, int E) {
    int e = blockIdx.x * blockDim.x + threadIdx.x;
    if (e >= E) return;
    int d = g_is64 ? (int)((const long long*)ei32)[E + e] : ei32[E + e];
    g_pos[e] = atomicAdd(&g_deg[d], 1);
}

// ---------------- dinv (hoisted so gemm1 can start early) ----------------
__global__ void k_dinv(int n) {
    int i = blockIdx.x * blockDim.x + threadIdx.x;
    if (i < n) g_dinv[i] = rsqrtf((float)g_deg[i] + 1.0f);  // +1 self-loop
}

// ---------------- scan (3-kernel, proven) ----------------
__global__ void k_partial(int n) {
    __shared__ int s[SCAN_B];
    int t = threadIdx.x;
    int i = blockIdx.x * SCAN_B + t;
    s[t] = (i < n) ? g_deg[i] : 0;
    __syncthreads();
    for (int d = SCAN_B / 2; d > 0; d >>= 1) {
        if (t < d) s[t] += s[t + d];
        __syncthreads();
    }
    if (t == 0) g_part[blockIdx.x] = s[0];
}

__global__ void k_scanpart(int nb, int n, int E) {
    __shared__ int s[MAX_PART];
    int t = threadIdx.x;
    s[t] = (t < nb) ? g_part[t] : 0;
    __syncthreads();
    for (int d = 1; d < MAX_PART; d <<= 1) {
        int v = (t >= d) ? s[t - d] : 0;
        __syncthreads();
        s[t] += v;
        __syncthreads();
    }
    if (t < nb) g_partoff[t] = (t == 0) ? 0 : s[t - 1];
    if (t == 0) g_off[n] = E;
}

__global__ void k_local(int n) {
    __shared__ int s[SCAN_B];
    int t = threadIdx.x;
    int i = blockIdx.x * SCAN_B + t;
    int deg = (i < n) ? g_deg[i] : 0;
    s[t] = deg;
    __syncthreads();
    for (int d = 1; d < SCAN_B; d <<= 1) {
        int v = (t >= d) ? s[t - d] : 0;
        __syncthreads();
        s[t] += v;
        __syncthreads();
    }
    if (i < n) g_off[i] = s[t] - deg + g_partoff[blockIdx.x];
}

// ---------------- CSR fill: NO atomics (rank precomputed) ----------------
__global__ void k_fill(const int* __restrict__ ei32, int E) {
    int e = blockIdx.x * blockDim.x + threadIdx.x;
    if (e >= E) return;
    int s, d;
    if (g_is64) {
        s = (int)((const long long*)ei32)[e];
        d = (int)((const long long*)ei32)[E + e];
    } else {
        s = ei32[e];
        d = ei32[E + e];
    }
    g_csr_src[g_off[d] + g_pos[e]] = s;
}

// ---------------- GEMM1: hs = (x@W1)*di (packed f32x2 FMA) ----------------
__global__ void k_gemm1(const float* __restrict__ x,
                        const float* __restrict__ W1, int n) {
    __shared__ __align__(16) float4 sW4[IN_CH * 8];   // 16 KB
    __shared__ __align__(16) float4 sx4[32 * 32];     // 16 KB
    int tid = threadIdx.x;
    int nodeBase = blockIdx.x * 32;

    for (int i = tid; i < IN_CH * 8; i += 256) sW4[i] = ((const float4*)W1)[i];
    for (int i = tid; i < 32 * 32; i += 256) {
        int nd = i >> 5, q = i & 31;
        int node = nodeBase + nd;
        sx4[i] = (node < n) ? ((const float4*)x)[(size_t)node * 32 + q]
                            : make_float4(0.f, 0.f, 0.f, 0.f);
    }
    __syncthreads();

    int nd = tid >> 3;
    int q = tid & 7;
    int node = nodeBase + nd;
    if (node >= n) return;

    const ulonglong2* sWu = (const ulonglong2*)sW4;
    unsigned long long a01 = 0ULL, a23 = 0ULL;
#pragma unroll 8
    for (int k4 = 0; k4 < 32; k4++) {
        float4 xv = sx4[nd * 32 + k4];
        unsigned long long d0 = pack2(xv.x, xv.x);
        unsigned long long d1 = pack2(xv.y, xv.y);
        unsigned long long d2 = pack2(xv.z, xv.z);
        unsigned long long d3 = pack2(xv.w, xv.w);
        ulonglong2 w0 = sWu[(4 * k4 + 0) * 8 + q];
        ulonglong2 w1 = sWu[(4 * k4 + 1) * 8 + q];
        ulonglong2 w2 = sWu[(4 * k4 + 2) * 8 + q];
        ulonglong2 w3 = sWu[(4 * k4 + 3) * 8 + q];
        a01 = fma2(d0, w0.x, a01); a23 = fma2(d0, w0.y, a23);
        a01 = fma2(d1, w1.x, a01); a23 = fma2(d1, w1.y, a23);
        a01 = fma2(d2, w2.x, a01); a23 = fma2(d2, w2.y, a23);
        a01 = fma2(d3, w3.x, a01); a23 = fma2(d3, w3.y, a23);
    }
    float2 lo = unpack2(a01), hi = unpack2(a23);
    float di = g_dinv[node];
    float4 hs = make_float4(lo.x * di, lo.y * di, hi.x * di, hi.y * di);
    ((float4*)g_h)[(size_t)node * 8 + q] = hs;
}

// ---------------- GEMM2: hs2 = (relu(acc)@W2)*di ----------------
__global__ void k_gemm2(const float* __restrict__ W2, int n) {
    __shared__ __align__(16) float4 sW4[HID * 8];
    __shared__ __align__(16) float4 sa4[32 * 8];
    int tid = threadIdx.x;
    int nodeBase = blockIdx.x * 32;

    for (int i = tid; i < HID * 8; i += 256) sW4[i] = ((const float4*)W2)[i];
    {
        int nd = tid >> 3, q = tid & 7;
        int node = nodeBase + nd;
        float4 v = make_float4(0.f, 0.f, 0.f, 0.f);
        if (node < n) {
            v = ((const float4*)g_acc)[(size_t)node * 8 + q];
            v.x = fmaxf(v.x, 0.f); v.y = fmaxf(v.y, 0.f);
            v.z = fmaxf(v.z, 0.f); v.w = fmaxf(v.w, 0.f);
        }
        sa4[nd * 8 + q] = v;
    }
    __syncthreads();

    int nd = tid >> 3;
    int q = tid & 7;
    int node = nodeBase + nd;
    if (node >= n) return;

    const ulonglong2* sWu = (const ulonglong2*)sW4;
    unsigned long long a01 = 0ULL, a23 = 0ULL;
#pragma unroll
    for (int k4 = 0; k4 < 8; k4++) {
        float4 xv = sa4[nd * 8 + k4];
        unsigned long long d0 = pack2(xv.x, xv.x);
        unsigned long long d1 = pack2(xv.y, xv.y);
        unsigned long long d2 = pack2(xv.z, xv.z);
        unsigned long long d3 = pack2(xv.w, xv.w);
        ulonglong2 w0 = sWu[(4 * k4 + 0) * 8 + q];
        ulonglong2 w1 = sWu[(4 * k4 + 1) * 8 + q];
        ulonglong2 w2 = sWu[(4 * k4 + 2) * 8 + q];
        ulonglong2 w3 = sWu[(4 * k4 + 3) * 8 + q];
        a01 = fma2(d0, w0.x, a01); a23 = fma2(d0, w0.y, a23);
        a01 = fma2(d1, w1.x, a01); a23 = fma2(d1, w1.y, a23);
        a01 = fma2(d2, w2.x, a01); a23 = fma2(d2, w2.y, a23);
        a01 = fma2(d3, w3.x, a01); a23 = fma2(d3, w3.y, a23);
    }
    float2 lo = unpack2(a01), hi = unpack2(a23);
    float di = g_dinv[node];
    float4 hs = make_float4(lo.x * di, lo.y * di, hi.x * di, hi.y * di);
    ((float4*)g_h)[(size_t)node * 8 + q] = hs;
}

// ---------------- aggregation: unroll 8, pure-store epilogue ----------------
__device__ __forceinline__ void aggregate_node(const float* __restrict__ bias,
                                               float* __restrict__ outrow,
                                               int node, int lane) {
    int j = lane >> 3;  // edge slot 0..3
    int q = lane & 7;   // float4 lane 0..7

    int beg = g_off[node];
    int end = g_off[node + 1];

    const float4* H = (const float4*)g_h;
    float4 acc = make_float4(0.f, 0.f, 0.f, 0.f);
#pragma unroll 8
    for (int i = beg + j; i < end; i += 4) {
        int s = g_csr_src[i];
        float4 v = __ldg(&H[(size_t)s * 8 + q]);
        acc.x += v.x; acc.y += v.y; acc.z += v.z; acc.w += v.w;
    }
#pragma unroll
    for (int m = 8; m <= 16; m <<= 1) {
        acc.x += __shfl_xor_sync(0xFFFFFFFFu, acc.x, m);
        acc.y += __shfl_xor_sync(0xFFFFFFFFu, acc.y, m);
        acc.z += __shfl_xor_sync(0xFFFFFFFFu, acc.z, m);
        acc.w += __shfl_xor_sync(0xFFFFFFFFu, acc.w, m);
    }
    if (j == 0) {
        float dd = g_dinv[node];
        float4 self = __ldg(&H[(size_t)node * 8 + q]);  // self-loop (hs)
        float4 bv = __ldg(((const float4*)bias) + q);
        float4 r;
        r.x = fmaf(dd, acc.x + self.x, bv.x);
        r.y = fmaf(dd, acc.y + self.y, bv.y);
        r.z = fmaf(dd, acc.z + self.z, bv.z);
        r.w = fmaf(dd, acc.w + self.w, bv.w);
        ((float4*)outrow)[q] = r;  // pure store
    }
}

__global__ void k_aggregate1(const float* __restrict__ b1, int n) {
    int warp_id = (blockIdx.x * blockDim.x + threadIdx.x) >> 5;
    if (warp_id >= n) return;
    aggregate_node(b1, g_acc + (size_t)warp_id * HID, warp_id, threadIdx.x & 31);
}

__global__ void k_aggregate2(const float* __restrict__ b2,
                             float* __restrict__ out, int n) {
    int warp_id = (blockIdx.x * blockDim.x + threadIdx.x) >> 5;
    if (warp_id >= n) return;
    aggregate_node(b2, out + (size_t)warp_id * HID, warp_id, threadIdx.x & 31);
}

extern "C" void kernel_launch(void* const* d_in, const int* in_sizes, int n_in,
                              void* d_out, int out_size) {
    const float* x  = (const float*)d_in[0];
    const int*   ei = (const int*)d_in[1];
    const float* W1 = (const float*)d_in[2];
    const float* b1 = (const float*)d_in[3];
    const float* W2 = (const float*)d_in[4];
    const float* b2 = (const float*)d_in[5];
    float* out = (float*)d_out;

    const int N = in_sizes[0] / IN_CH;
    const int E = in_sizes[1] / 2;
    const int nb = (N + SCAN_B - 1) / SCAN_B;

    // --- serial prologue on the main (capture) stream ---
    k_detect_zero<<<(N + 255) / 256, 256>>>(ei, E, N);
    k_deg<<<(E + 255) / 256, 256>>>(ei, E);
    k_dinv<<<(N + 255) / 256, 256>>>(N);

    // --- fork: gemm1 (needs only x, W1, dinv) overlaps the CSR build ---
    cudaStream_t s2;
    cudaStreamCreateWithFlags(&s2, cudaStreamNonBlocking);
    cudaEvent_t evFork, evJoin;
    cudaEventCreateWithFlags(&evFork, cudaEventDisableTiming);
    cudaEventCreateWithFlags(&evJoin, cudaEventDisableTiming);

    cudaEventRecord(evFork, 0);
    cudaStreamWaitEvent(s2, evFork, 0);
    k_gemm1<<<(N + 31) / 32, 256, 0, s2>>>(x, W1, N);
    cudaEventRecord(evJoin, s2);

    k_partial<<<nb, SCAN_B>>>(N);
    k_scanpart<<<1, MAX_PART>>>(nb, N, E);
    k_local<<<nb, SCAN_B>>>(N);
    k_fill<<<(E + 255) / 256, 256>>>(ei, E);

    cudaStreamWaitEvent(0, evJoin, 0);   // join before aggregation

    // --- layer 1 aggregate, layer 2 ---
    {
        long long thr = (long long)N * 32;
        k_aggregate1<<<(int)((thr + 255) / 256), 256>>>(b1, N);
    }
    k_gemm2<<<(N + 31) / 32, 256>>>(W2, N);
    {
        long long thr = (long long)N * 32;
        k_aggregate2<<<(int)((thr + 255) / 256), 256>>>(b2, out, N);
    }

    cudaEventDestroy(evFork);
    cudaEventDestroy(evJoin);
    cudaStreamDestroy(s2);
}

// round 11
// speedup vs baseline: 1.1107x; 1.1107x over previous
#include <cuda_runtime.h>
#include <cstdint>

#define N_NODES 100000
#define IN_CH 128
#define HID 32
#define MAX_E 3400000
#define SCAN_B 1024
#define MAX_PART 128
#define G_THREADS 128
#define G_NODES 64

// ---- scratch: device globals. Referenced ONLY from device code. ----
__device__ __align__(16) float g_h[N_NODES * HID];    // hs = (x@W)*dinv per layer
__device__ __align__(16) float g_acc[N_NODES * HID];  // layer-1 aggregated output
__device__ int   g_deg[N_NODES];
__device__ float g_dinv[N_NODES];
__device__ int   g_off[N_NODES + 1];
__device__ int   g_csr_src[MAX_E];
__device__ int   g_pos[MAX_E];
__device__ int   g_part[MAX_PART];
__device__ int   g_partoff[MAX_PART];
__device__ int   g_is64;

// ---- packed f32x2 helpers (Blackwell FFMA2) ----
__device__ __forceinline__ unsigned long long pack2(float a, float b) {
    unsigned long long r;
    asm("mov.b64 %0, {%1, %2};" : "=l"(r) : "f"(a), "f"(b));
    return r;
}
__device__ __forceinline__ unsigned long long fma2(unsigned long long a,
                                                   unsigned long long b,
                                                   unsigned long long c) {
    unsigned long long d;
    asm("fma.rn.f32x2 %0, %1, %2, %3;" : "=l"(d) : "l"(a), "l"(b), "l"(c));
    return d;
}
__device__ __forceinline__ float2 unpack2(unsigned long long v) {
    float2 f;
    asm("mov.b64 {%0, %1}, %2;" : "=f"(f.x), "=f"(f.y) : "l"(v));
    return f;
}

// ---------------- dtype probe + zero deg (fused) ----------------
__global__ void k_detect_zero(const int* __restrict__ ei32, int E, int n) {
    int i = blockIdx.x * blockDim.x + threadIdx.x;
    if (i < n) g_deg[i] = 0;
    if (blockIdx.x == 0) {
        __shared__ int nz;
        if (threadIdx.x == 0) nz = 0;
        __syncthreads();
        int m = (E > 256) ? 256 : E;
        if (threadIdx.x < m) {
            if (ei32[2 * threadIdx.x + 1] != 0) nz = 1;  // benign race
        }
        __syncthreads();
        if (threadIdx.x == 0) g_is64 = (nz == 0);
    }
}

// ---------------- degree + per-edge bucket rank ----------------
__global__ void k_deg(const int* __restrict__ ei32, int E) {
    int e = blockIdx.x * blockDim.x + threadIdx.x;
    if (e >= E) return;
    int d = g_is64 ? (int)((const long long*)ei32)[E + e] : ei32[E + e];
    g_pos[e] = atomicAdd(&g_deg[d], 1);
}

// ---------------- scan (3-kernel, proven) ----------------
__global__ void k_partial(int n) {
    __shared__ int s[SCAN_B];
    int t = threadIdx.x;
    int i = blockIdx.x * SCAN_B + t;
    s[t] = (i < n) ? g_deg[i] : 0;
    __syncthreads();
    for (int d = SCAN_B / 2; d > 0; d >>= 1) {
        if (t < d) s[t] += s[t + d];
        __syncthreads();
    }
    if (t == 0) g_part[blockIdx.x] = s[0];
}

__global__ void k_scanpart(int nb, int n, int E) {
    __shared__ int s[MAX_PART];
    int t = threadIdx.x;
    s[t] = (t < nb) ? g_part[t] : 0;
    __syncthreads();
    for (int d = 1; d < MAX_PART; d <<= 1) {
        int v = (t >= d) ? s[t - d] : 0;
        __syncthreads();
        s[t] += v;
        __syncthreads();
    }
    if (t < nb) g_partoff[t] = (t == 0) ? 0 : s[t - 1];
    if (t == 0) g_off[n] = E;
}

__global__ void k_local(int n) {
    __shared__ int s[SCAN_B];
    int t = threadIdx.x;
    int i = blockIdx.x * SCAN_B + t;
    int deg = (i < n) ? g_deg[i] : 0;
    s[t] = deg;
    __syncthreads();
    for (int d = 1; d < SCAN_B; d <<= 1) {
        int v = (t >= d) ? s[t - d] : 0;
        __syncthreads();
        s[t] += v;
        __syncthreads();
    }
    if (i < n) {
        g_off[i] = s[t] - deg + g_partoff[blockIdx.x];
        g_dinv[i] = rsqrtf((float)deg + 1.0f);  // +1 self-loop
    }
}

// ---------------- CSR fill: NO atomics ----------------
__global__ void k_fill(const int* __restrict__ ei32, int E) {
    int e = blockIdx.x * blockDim.x + threadIdx.x;
    if (e >= E) return;
    int s, d;
    if (g_is64) {
        s = (int)((const long long*)ei32)[e];
        d = (int)((const long long*)ei32)[E + e];
    } else {
        s = ei32[e];
        d = ei32[E + e];
    }
    g_csr_src[g_off[d] + g_pos[e]] = s;
}

// ---------------- GEMM1: hs = (x@W1)*di; 4 nodes/thread (LDS-traffic cut) --------
__global__ void __launch_bounds__(G_THREADS)
k_gemm1(const float* __restrict__ x, const float* __restrict__ W1, int n) {
    __shared__ __align__(16) float4 sW4[IN_CH * 8];       // 16 KB: W1[k][4q..4q+3]
    __shared__ __align__(16) float4 sx4[G_NODES * 32];    // 32 KB
    int tid = threadIdx.x;
    int nodeBase = blockIdx.x * G_NODES;

    for (int i = tid; i < IN_CH * 8; i += G_THREADS) sW4[i] = ((const float4*)W1)[i];
    for (int i = tid; i < G_NODES * 32; i += G_THREADS) {
        int nd = i >> 5, kq = i & 31;
        int node = nodeBase + nd;
        sx4[i] = (node < n) ? ((const float4*)x)[(size_t)node * 32 + kq]
                            : make_float4(0.f, 0.f, 0.f, 0.f);
    }
    __syncthreads();

    int g = tid >> 3;       // 0..15, owns 4 nodes
    int q = tid & 7;        // output quad
    const ulonglong2* sWu = (const ulonglong2*)sW4;
    const float4* x0 = sx4 + (g * 4 + 0) * 32;
    const float4* x1 = sx4 + (g * 4 + 1) * 32;
    const float4* x2 = sx4 + (g * 4 + 2) * 32;
    const float4* x3 = sx4 + (g * 4 + 3) * 32;

    unsigned long long a0x = 0, a0y = 0, a1x = 0, a1y = 0;
    unsigned long long a2x = 0, a2y = 0, a3x = 0, a3y = 0;
#pragma unroll 4
    for (int k4 = 0; k4 < 32; k4++) {
        ulonglong2 w0 = sWu[(4 * k4 + 0) * 8 + q];
        ulonglong2 w1 = sWu[(4 * k4 + 1) * 8 + q];
        ulonglong2 w2 = sWu[(4 * k4 + 2) * 8 + q];
        ulonglong2 w3 = sWu[(4 * k4 + 3) * 8 + q];
        {
            float4 xv = x0[k4];
            unsigned long long d;
            d = pack2(xv.x, xv.x); a0x = fma2(d, w0.x, a0x); a0y = fma2(d, w0.y, a0y);
            d = pack2(xv.y, xv.y); a0x = fma2(d, w1.x, a0x); a0y = fma2(d, w1.y, a0y);
            d = pack2(xv.z, xv.z); a0x = fma2(d, w2.x, a0x); a0y = fma2(d, w2.y, a0y);
            d = pack2(xv.w, xv.w); a0x = fma2(d, w3.x, a0x); a0y = fma2(d, w3.y, a0y);
        }
        {
            float4 xv = x1[k4];
            unsigned long long d;
            d = pack2(xv.x, xv.x); a1x = fma2(d, w0.x, a1x); a1y = fma2(d, w0.y, a1y);
            d = pack2(xv.y, xv.y); a1x = fma2(d, w1.x, a1x); a1y = fma2(d, w1.y, a1y);
            d = pack2(xv.z, xv.z); a1x = fma2(d, w2.x, a1x); a1y = fma2(d, w2.y, a1y);
            d = pack2(xv.w, xv.w); a1x = fma2(d, w3.x, a1x); a1y = fma2(d, w3.y, a1y);
        }
        {
            float4 xv = x2[k4];
            unsigned long long d;
            d = pack2(xv.x, xv.x); a2x = fma2(d, w0.x, a2x); a2y = fma2(d, w0.y, a2y);
            d = pack2(xv.y, xv.y); a2x = fma2(d, w1.x, a2x); a2y = fma2(d, w1.y, a2y);
            d = pack2(xv.z, xv.z); a2x = fma2(d, w2.x, a2x); a2y = fma2(d, w2.y, a2y);
            d = pack2(xv.w, xv.w); a2x = fma2(d, w3.x, a2x); a2y = fma2(d, w3.y, a2y);
        }
        {
            float4 xv = x3[k4];
            unsigned long long d;
            d = pack2(xv.x, xv.x); a3x = fma2(d, w0.x, a3x); a3y = fma2(d, w0.y, a3y);
            d = pack2(xv.y, xv.y); a3x = fma2(d, w1.x, a3x); a3y = fma2(d, w1.y, a3y);
            d = pack2(xv.z, xv.z); a3x = fma2(d, w2.x, a3x); a3y = fma2(d, w2.y, a3y);
            d = pack2(xv.w, xv.w); a3x = fma2(d, w3.x, a3x); a3y = fma2(d, w3.y, a3y);
        }
    }

#define G1_STORE(r, ax, ay)                                                   \
    {                                                                          \
        int node = nodeBase + g * 4 + r;                                       \
        if (node < n) {                                                        \
            float di = g_dinv[node];                                           \
            float2 lo = unpack2(ax), hi = unpack2(ay);                         \
            float4 hs = make_float4(lo.x * di, lo.y * di, hi.x * di, hi.y * di);\
            ((float4*)g_h)[(size_t)node * 8 + q] = hs;                         \
        }                                                                      \
    }
    G1_STORE(0, a0x, a0y)
    G1_STORE(1, a1x, a1y)
    G1_STORE(2, a2x, a2y)
    G1_STORE(3, a3x, a3y)
#undef G1_STORE
}

// ---------------- GEMM2: hs2 = (relu(acc)@W2)*di; 4 nodes/thread ----------------
__global__ void __launch_bounds__(G_THREADS)
k_gemm2(const float* __restrict__ W2, int n) {
    __shared__ __align__(16) float4 sW4[HID * 8];        // 4 KB
    __shared__ __align__(16) float4 sa4[G_NODES * 8];    // 8 KB
    int tid = threadIdx.x;
    int nodeBase = blockIdx.x * G_NODES;

    for (int i = tid; i < HID * 8; i += G_THREADS) sW4[i] = ((const float4*)W2)[i];
    for (int i = tid; i < G_NODES * 8; i += G_THREADS) {
        int nd = i >> 3, kq = i & 7;
        int node = nodeBase + nd;
        float4 v = make_float4(0.f, 0.f, 0.f, 0.f);
        if (node < n) {
            v = ((const float4*)g_acc)[(size_t)node * 8 + kq];
            v.x = fmaxf(v.x, 0.f); v.y = fmaxf(v.y, 0.f);
            v.z = fmaxf(v.z, 0.f); v.w = fmaxf(v.w, 0.f);
        }
        sa4[i] = v;
    }
    __syncthreads();

    int g = tid >> 3;
    int q = tid & 7;
    const ulonglong2* sWu = (const ulonglong2*)sW4;
    const float4* x0 = sa4 + (g * 4 + 0) * 8;
    const float4* x1 = sa4 + (g * 4 + 1) * 8;
    const float4* x2 = sa4 + (g * 4 + 2) * 8;
    const float4* x3 = sa4 + (g * 4 + 3) * 8;

    unsigned long long a0x = 0, a0y = 0, a1x = 0, a1y = 0;
    unsigned long long a2x = 0, a2y = 0, a3x = 0, a3y = 0;
#pragma unroll
    for (int k4 = 0; k4 < 8; k4++) {
        ulonglong2 w0 = sWu[(4 * k4 + 0) * 8 + q];
        ulonglong2 w1 = sWu[(4 * k4 + 1) * 8 + q];
        ulonglong2 w2 = sWu[(4 * k4 + 2) * 8 + q];
        ulonglong2 w3 = sWu[(4 * k4 + 3) * 8 + q];
        {
            float4 xv = x0[k4];
            unsigned long long d;
            d = pack2(xv.x, xv.x); a0x = fma2(d, w0.x, a0x); a0y = fma2(d, w0.y, a0y);
            d = pack2(xv.y, xv.y); a0x = fma2(d, w1.x, a0x); a0y = fma2(d, w1.y, a0y);
            d = pack2(xv.z, xv.z); a0x = fma2(d, w2.x, a0x); a0y = fma2(d, w2.y, a0y);
            d = pack2(xv.w, xv.w); a0x = fma2(d, w3.x, a0x); a0y = fma2(d, w3.y, a0y);
        }
        {
            float4 xv = x1[k4];
            unsigned long long d;
            d = pack2(xv.x, xv.x); a1x = fma2(d, w0.x, a1x); a1y = fma2(d, w0.y, a1y);
            d = pack2(xv.y, xv.y); a1x = fma2(d, w1.x, a1x); a1y = fma2(d, w1.y, a1y);
            d = pack2(xv.z, xv.z); a1x = fma2(d, w2.x, a1x); a1y = fma2(d, w2.y, a1y);
            d = pack2(xv.w, xv.w); a1x = fma2(d, w3.x, a1x); a1y = fma2(d, w3.y, a1y);
        }
        {
            float4 xv = x2[k4];
            unsigned long long d;
            d = pack2(xv.x, xv.x); a2x = fma2(d, w0.x, a2x); a2y = fma2(d, w0.y, a2y);
            d = pack2(xv.y, xv.y); a2x = fma2(d, w1.x, a2x); a2y = fma2(d, w1.y, a2y);
            d = pack2(xv.z, xv.z); a2x = fma2(d, w2.x, a2x); a2y = fma2(d, w2.y, a2y);
            d = pack2(xv.w, xv.w); a2x = fma2(d, w3.x, a2x); a2y = fma2(d, w3.y, a2y);
        }
        {
            float4 xv = x3[k4];
            unsigned long long d;
            d = pack2(xv.x, xv.x); a3x = fma2(d, w0.x, a3x); a3y = fma2(d, w0.y, a3y);
            d = pack2(xv.y, xv.y); a3x = fma2(d, w1.x, a3x); a3y = fma2(d, w1.y, a3y);
            d = pack2(xv.z, xv.z); a3x = fma2(d, w2.x, a3x); a3y = fma2(d, w2.y, a3y);
            d = pack2(xv.w, xv.w); a3x = fma2(d, w3.x, a3x); a3y = fma2(d, w3.y, a3y);
        }
    }

#define G2_STORE(r, ax, ay)                                                   \
    {                                                                          \
        int node = nodeBase + g * 4 + r;                                       \
        if (node < n) {                                                        \
            float di = g_dinv[node];                                           \
            float2 lo = unpack2(ax), hi = unpack2(ay);                         \
            float4 hs = make_float4(lo.x * di, lo.y * di, hi.x * di, hi.y * di);\
            ((float4*)g_h)[(size_t)node * 8 + q] = hs;                         \
        }                                                                      \
    }
    G2_STORE(0, a0x, a0y)
    G2_STORE(1, a1x, a1y)
    G2_STORE(2, a2x, a2y)
    G2_STORE(3, a3x, a3y)
#undef G2_STORE
}

// ---------------- aggregation (R9-proven): unroll 4, pure-store epilogue ----------
__device__ __forceinline__ void aggregate_node(const float* __restrict__ bias,
                                               float* __restrict__ outrow,
                                               int node, int lane) {
    int j = lane >> 3;
    int q = lane & 7;

    int beg = g_off[node];
    int end = g_off[node + 1];

    const float4* H = (const float4*)g_h;
    float4 acc = make_float4(0.f, 0.f, 0.f, 0.f);
#pragma unroll 4
    for (int i = beg + j; i < end; i += 4) {
        int s = g_csr_src[i];
        float4 v = __ldg(&H[(size_t)s * 8 + q]);
        acc.x += v.x; acc.y += v.y; acc.z += v.z; acc.w += v.w;
    }
#pragma unroll
    for (int m = 8; m <= 16; m <<= 1) {
        acc.x += __shfl_xor_sync(0xFFFFFFFFu, acc.x, m);
        acc.y += __shfl_xor_sync(0xFFFFFFFFu, acc.y, m);
        acc.z += __shfl_xor_sync(0xFFFFFFFFu, acc.z, m);
        acc.w += __shfl_xor_sync(0xFFFFFFFFu, acc.w, m);
    }
    if (j == 0) {
        float dd = g_dinv[node];
        float4 self = __ldg(&H[(size_t)node * 8 + q]);
        float4 bv = __ldg(((const float4*)bias) + q);
        float4 r;
        r.x = fmaf(dd, acc.x + self.x, bv.x);
        r.y = fmaf(dd, acc.y + self.y, bv.y);
        r.z = fmaf(dd, acc.z + self.z, bv.z);
        r.w = fmaf(dd, acc.w + self.w, bv.w);
        ((float4*)outrow)[q] = r;
    }
}

__global__ void k_aggregate1(const float* __restrict__ b1, int n) {
    int warp_id = (blockIdx.x * blockDim.x + threadIdx.x) >> 5;
    if (warp_id >= n) return;
    aggregate_node(b1, g_acc + (size_t)warp_id * HID, warp_id, threadIdx.x & 31);
}

__global__ void k_aggregate2(const float* __restrict__ b2,
                             float* __restrict__ out, int n) {
    int warp_id = (blockIdx.x * blockDim.x + threadIdx.x) >> 5;
    if (warp_id >= n) return;
    aggregate_node(b2, out + (size_t)warp_id * HID, warp_id, threadIdx.x & 31);
}

extern "C" void kernel_launch(void* const* d_in, const int* in_sizes, int n_in,
                              void* d_out, int out_size) {
    const float* x  = (const float*)d_in[0];
    const int*   ei = (const int*)d_in[1];
    const float* W1 = (const float*)d_in[2];
    const float* b1 = (const float*)d_in[3];
    const float* W2 = (const float*)d_in[4];
    const float* b2 = (const float*)d_in[5];
    float* out = (float*)d_out;

    const int N = in_sizes[0] / IN_CH;
    const int E = in_sizes[1] / 2;
    const int nb = (N + SCAN_B - 1) / SCAN_B;

    k_detect_zero<<<(N + 255) / 256, 256>>>(ei, E, N);
    k_deg<<<(E + 255) / 256, 256>>>(ei, E);

    k_partial<<<nb, SCAN_B>>>(N);
    k_scanpart<<<1, MAX_PART>>>(nb, N, E);
    k_local<<<nb, SCAN_B>>>(N);

    k_fill<<<(E + 255) / 256, 256>>>(ei, E);

    k_gemm1<<<(N + G_NODES - 1) / G_NODES, G_THREADS>>>(x, W1, N);
    {
        long long thr = (long long)N * 32;
        k_aggregate1<<<(int)((thr + 255) / 256), 256>>>(b1, N);
    }

    k_gemm2<<<(N + G_NODES - 1) / G_NODES, G_THREADS>>>(W2, N);
    {
        long long thr = (long long)N * 32;
        k_aggregate2<<<(int)((thr + 255) / 256), 256>>>(b2, out, N);
    }
}